// round 6
// baseline (speedup 1.0000x reference)
#include <cuda_runtime.h>
#include <math.h>

#define BB 8
#define CC 128
#define HH 128
#define WW 128
#define HWs 16384
#define RR 4
#define KK 9

// ---------------- scratch (static __device__, no allocation) ----------------
__device__ float g_x1[BB * CC * HWs];     // conv1 out / gn1+silu (in place)
__device__ float g_x2[BB * 64 * HWs];     // conv2 out / gn2+silu
__device__ float g_pred[BB * 3 * HWs];    // offset head output
__device__ float g_cv[BB * 81 * HWs];     // cost volume
__device__ float g_ce[BB * 64 * HWs];     // corr embed
__device__ float g_de[BB * 64 * HWs];     // diff embed
__device__ float g_f[BB * CC * HWs];      // fusion conv out
__device__ float g_mean[256];
__device__ float g_rstd[256];
__device__ float g_weff[128];             // lam_w @ fus_w2 composed

__device__ __forceinline__ float sigmoidf_(float x) { return 1.f / (1.f + expf(-x)); }

// ---------------- generic 3x3 conv, pad=1, 2 channels per stage ----------------
// grid: (64 tiles, Cout/16, B), block 256.
// Each thread: 1 output channel x 4x4 pixel patch (16 accumulators).
__global__ void conv3x3_k(const float* __restrict__ in1, const float* __restrict__ in2,
                          int Cin1, int Cin2, const float* __restrict__ wgt,
                          float* __restrict__ out, int Cout) {
  __shared__ float s_in[2][18 * 18];
  __shared__ float s_w[2][144];
  const int Cin = Cin1 + Cin2;  // always even here
  int b = blockIdx.z;
  int co_base = blockIdx.y * 16;
  int tile = blockIdx.x;
  int ty0 = (tile >> 3) << 4;
  int tx0 = (tile & 7) << 4;
  int tid = threadIdx.x;
  int co = tid >> 4;
  int pg = tid & 15;
  int pr0 = (pg >> 2) << 2;
  int pc0 = (pg & 3) << 2;
  float acc[16];
#pragma unroll
  for (int i = 0; i < 16; i++) acc[i] = 0.f;

  for (int ci = 0; ci < Cin; ci += 2) {
    __syncthreads();
    for (int i = tid; i < 648; i += 256) {
      int buf = (i >= 324) ? 1 : 0;
      int j = i - buf * 324;
      int r = j / 18, c = j - r * 18;
      int cc2 = ci + buf;
      const float* plane = (cc2 < Cin1)
          ? in1 + ((size_t)b * Cin1 + cc2) * HWs
          : in2 + ((size_t)b * Cin2 + (cc2 - Cin1)) * HWs;
      int gy = ty0 + r - 1, gx = tx0 + c - 1;
      float v = 0.f;
      if (gy >= 0 && gy < HH && gx >= 0 && gx < WW) v = plane[gy * WW + gx];
      s_in[buf][j] = v;
    }
    // FIX (R2): strided loop — previous `if (tid < 288)` with 256 threads left
    // s_w[1][112..143] uninitialized -> NaN.
    for (int i = tid; i < 288; i += 256) {
      int buf = (i >= 144) ? 1 : 0;
      int j = i - buf * 144;
      int c2 = j / 9, k = j - c2 * 9;
      s_w[buf][j] = wgt[((size_t)(co_base + c2) * Cin + ci + buf) * 9 + k];
    }
    __syncthreads();
#pragma unroll
    for (int buf = 0; buf < 2; buf++) {
      float wreg[9];
#pragma unroll
      for (int k = 0; k < 9; k++) wreg[k] = s_w[buf][co * 9 + k];
      float patch[6][6];
#pragma unroll
      for (int r = 0; r < 6; r++)
#pragma unroll
        for (int c = 0; c < 6; c++)
          patch[r][c] = s_in[buf][(pr0 + r) * 18 + pc0 + c];
#pragma unroll
      for (int ky = 0; ky < 3; ky++)
#pragma unroll
        for (int kx = 0; kx < 3; kx++) {
          float wv = wreg[ky * 3 + kx];
#pragma unroll
          for (int pr = 0; pr < 4; pr++)
#pragma unroll
            for (int pc = 0; pc < 4; pc++)
              acc[pr * 4 + pc] += patch[pr + ky][pc + kx] * wv;
        }
    }
  }
  float* op = out + ((size_t)b * Cout + co_base + co) * HWs;
#pragma unroll
  for (int pr = 0; pr < 4; pr++)
#pragma unroll
    for (int pc = 0; pc < 4; pc++)
      op[(ty0 + pr0 + pr) * WW + tx0 + pc0 + pc] = acc[pr * 4 + pc];
}

// ---------------- GroupNorm stats (one block per (b, group)) ----------------
__global__ void gn_stats_k(const float* __restrict__ x, int C, int G) {
  __shared__ double s_s[256];
  __shared__ double s_q[256];
  int bg = blockIdx.x;
  int b = bg / G, g = bg % G;
  int cpg = C / G;
  long n = (long)cpg * HWs;
  const float* base = x + ((size_t)b * C + (size_t)g * cpg) * HWs;
  double s = 0, q = 0;
  for (long i = threadIdx.x; i < n; i += 256) {
    double v = base[i];
    s += v;
    q += v * v;
  }
  s_s[threadIdx.x] = s;
  s_q[threadIdx.x] = q;
  __syncthreads();
  for (int off = 128; off > 0; off >>= 1) {
    if (threadIdx.x < off) {
      s_s[threadIdx.x] += s_s[threadIdx.x + off];
      s_q[threadIdx.x] += s_q[threadIdx.x + off];
    }
    __syncthreads();
  }
  if (threadIdx.x == 0) {
    double m = s_s[0] / (double)n;
    double var = s_q[0] / (double)n - m * m;
    g_mean[bg] = (float)m;
    g_rstd[bg] = (float)rsqrt(var + 1e-5);
  }
}

// ---------------- GroupNorm apply + activation (0=silu, 1=relu) -------------
__global__ void gn_act_k(float* __restrict__ x, const float* __restrict__ gamma,
                         const float* __restrict__ beta, int C, int G, int act) {
  long idx = (long)blockIdx.x * 256 + threadIdx.x;
  int cpg = C / G;
  long chw = (long)C * HWs;
  int b = (int)(idx / chw);
  int c = (int)((idx % chw) / HWs);
  int bg = b * G + c / cpg;
  float v = x[idx];
  v = (v - g_mean[bg]) * g_rstd[bg] * gamma[c] + beta[c];
  if (act == 0)
    v = v * sigmoidf_(v);
  else
    v = fmaxf(v, 0.f);
  x[idx] = v;
}

// ---------------- offset head final conv (64 -> 3, 3x3, pad=1) + bias -------
__global__ void pred_conv_k(const float* __restrict__ in, const float* __restrict__ wgt,
                            const float* __restrict__ bias, float* __restrict__ out) {
  __shared__ float s_w[576];
  int co = blockIdx.y, b = blockIdx.z;
  for (int i = threadIdx.x; i < 576; i += 256) s_w[i] = wgt[co * 576 + i];
  __syncthreads();
  int p = blockIdx.x * 256 + threadIdx.x;
  int h = p >> 7, w = p & 127;
  float acc = bias[co];
  for (int ci = 0; ci < 64; ci++) {
    const float* pl = in + ((size_t)b * 64 + ci) * HWs;
#pragma unroll
    for (int ky = 0; ky < 3; ky++) {
      int y = h + ky - 1;
      if (y < 0 || y >= HH) continue;
#pragma unroll
      for (int kx = 0; kx < 3; kx++) {
        int xx = w + kx - 1;
        if (xx < 0 || xx >= WW) continue;
        acc += pl[y * WW + xx] * s_w[ci * 9 + ky * 3 + kx];
      }
    }
  }
  out[((size_t)b * 3 + co) * HWs + p] = acc;
}

// ---------------- flow + validity + bilinear warp ----------------
__global__ void warp_k(const float* __restrict__ feat2, const float* __restrict__ pred,
                       float* __restrict__ out_aligned, float* __restrict__ out_flow) {
  int b = blockIdx.y;
  int p = blockIdx.x * 256 + threadIdx.x;
  int h = p >> 7, w = p & 127;
  const float* pb = pred + (size_t)b * 3 * HWs;
  float f0 = pb[p], f1 = pb[HWs + p], pv = pb[2 * HWs + p];
  float val = sigmoidf_(pv);
  out_flow[((size_t)b * 2) * HWs + p] = f0;
  out_flow[((size_t)b * 2 + 1) * HWs + p] = f1;
  float px = (float)w + f0, py = (float)h + f1;
  float x0f = floorf(px), y0f = floorf(py);
  float wx = px - x0f, wy = py - y0f;
  int x0 = (int)x0f, y0 = (int)y0f;
  bool vx0 = (x0 >= 0) && (x0 < WW);
  bool vx1 = (x0 + 1 >= 0) && (x0 + 1 < WW);
  bool vy0 = (y0 >= 0) && (y0 < HH);
  bool vy1 = (y0 + 1 >= 0) && (y0 + 1 < HH);
  int xc0 = min(max(x0, 0), WW - 1), xc1 = min(max(x0 + 1, 0), WW - 1);
  int yc0 = min(max(y0, 0), HH - 1), yc1 = min(max(y0 + 1, 0), HH - 1);
  float w00 = (1.f - wx) * (1.f - wy) * ((vx0 && vy0) ? 1.f : 0.f);
  float w10 = wx * (1.f - wy) * ((vx1 && vy0) ? 1.f : 0.f);
  float w01 = (1.f - wx) * wy * ((vx0 && vy1) ? 1.f : 0.f);
  float w11 = wx * wy * ((vx1 && vy1) ? 1.f : 0.f);
  int i00 = yc0 * WW + xc0, i10 = yc0 * WW + xc1;
  int i01 = yc1 * WW + xc0, i11 = yc1 * WW + xc1;
  const float* f2b = feat2 + (size_t)b * CC * HWs;
  float* ob = out_aligned + (size_t)b * CC * HWs;
  for (int c = 0; c < CC; c++) {
    const float* im = f2b + (size_t)c * HWs;
    float s = __ldg(&im[i00]) * w00 + __ldg(&im[i10]) * w10 +
              __ldg(&im[i01]) * w01 + __ldg(&im[i11]) * w11;
    ob[(size_t)c * HWs + p] = s * val;
  }
}

// ---------------- cost volume: tiled, 81 accumulators per thread ----------------
// grid: (64 tiles, B), block 256 = 16x16 pixels.
__global__ void costvol_k(const float* __restrict__ f1, const float* __restrict__ aligned,
                          float* __restrict__ cv) {
  __shared__ float s_al[24 * 24];
  int b = blockIdx.y;
  int tile = blockIdx.x;
  int ty0 = (tile >> 3) << 4;
  int tx0 = (tile & 7) << 4;
  int tid = threadIdx.x;
  int ty = tid >> 4, tx = tid & 15;
  float acc[81];
#pragma unroll
  for (int k = 0; k < 81; k++) acc[k] = 0.f;

  for (int c = 0; c < CC; c++) {
    const float* apl = aligned + ((size_t)b * CC + c) * HWs;
    __syncthreads();
    for (int i = tid; i < 576; i += 256) {
      int r = i / 24, cc = i - r * 24;
      int gy = ty0 + r - RR, gx = tx0 + cc - RR;
      float v = 0.f;
      if (gy >= 0 && gy < HH && gx >= 0 && gx < WW) v = apl[gy * WW + gx];
      s_al[i] = v;
    }
    __syncthreads();
    float f1v = f1[((size_t)b * CC + c) * HWs + (ty0 + ty) * WW + tx0 + tx];
#pragma unroll
    for (int dy = 0; dy < KK; dy++)
#pragma unroll
      for (int dx = 0; dx < KK; dx++)
        acc[dy * KK + dx] += f1v * s_al[(ty + dy) * 24 + tx + dx];
  }
  size_t pbase = (size_t)(ty0 + ty) * WW + tx0 + tx;
#pragma unroll
  for (int k = 0; k < 81; k++)
    cv[((size_t)b * 81 + k) * HWs + pbase] = acc[k] * (1.f / (float)CC);
}

// ---------------- generic 1x1 conv to 64 channels ----------------
__global__ void conv1x1_64_k(const float* __restrict__ in, const float* __restrict__ wgt,
                             float* __restrict__ out, int Cin) {
  __shared__ float s_w[64 * 128];
  int b = blockIdx.y;
  for (int i = threadIdx.x; i < 64 * Cin; i += 256) s_w[i] = wgt[i];
  __syncthreads();
  int p = blockIdx.x * 256 + threadIdx.x;
  float acc[64];
#pragma unroll
  for (int i = 0; i < 64; i++) acc[i] = 0.f;
  const float* ib = in + (size_t)b * Cin * HWs + p;
  for (int ci = 0; ci < Cin; ci++) {
    float v = __ldg(&ib[(size_t)ci * HWs]);
#pragma unroll
    for (int co = 0; co < 64; co++) acc[co] += v * s_w[co * Cin + ci];
  }
  float* ob = out + (size_t)b * 64 * HWs + p;
#pragma unroll
  for (int co = 0; co < 64; co++) ob[(size_t)co * HWs] = acc[co];
}

// ---------------- diff (|f1 - aligned|) then 1x1 conv 128->64 ----------------
__global__ void diffconv_k(const float* __restrict__ f1, const float* __restrict__ aligned,
                           const float* __restrict__ wgt, float* __restrict__ out) {
  __shared__ float s_w[64 * 128];
  int b = blockIdx.y;
  for (int i = threadIdx.x; i < 64 * 128; i += 256) s_w[i] = wgt[i];
  __syncthreads();
  int p = blockIdx.x * 256 + threadIdx.x;
  float acc[64];
#pragma unroll
  for (int i = 0; i < 64; i++) acc[i] = 0.f;
  const float* fb = f1 + (size_t)b * CC * HWs + p;
  const float* ab = aligned + (size_t)b * CC * HWs + p;
  for (int ci = 0; ci < 128; ci++) {
    float v = fabsf(__ldg(&fb[(size_t)ci * HWs]) - __ldg(&ab[(size_t)ci * HWs]));
#pragma unroll
    for (int co = 0; co < 64; co++) acc[co] += v * s_w[co * 128 + ci];
  }
  float* ob = out + (size_t)b * 64 * HWs + p;
#pragma unroll
  for (int co = 0; co < 64; co++) ob[(size_t)co * HWs] = acc[co];
}

// ---------------- compose lam_w @ fus_w2 (both 1x1) ----------------
__global__ void weff_k(const float* __restrict__ fus_w2, const float* __restrict__ lam_w) {
  int ci = threadIdx.x;  // 128 threads
  float s = 0.f;
  for (int co = 0; co < 128; co++) s += lam_w[co] * fus_w2[co * 128 + ci];
  g_weff[ci] = s;
}

// ---------------- lam = sigmoid(f . weff + b) ----------------
__global__ void lam_k(const float* __restrict__ f, const float* __restrict__ lam_b,
                      float* __restrict__ out) {
  __shared__ float s_w[128];
  if (threadIdx.x < 128) s_w[threadIdx.x] = g_weff[threadIdx.x];
  __syncthreads();
  int b = blockIdx.y;
  int p = blockIdx.x * 256 + threadIdx.x;
  const float* fb = f + (size_t)b * 128 * HWs + p;
  float acc = lam_b[0];
  for (int ci = 0; ci < 128; ci++) acc += __ldg(&fb[(size_t)ci * HWs]) * s_w[ci];
  out[(size_t)b * HWs + p] = sigmoidf_(acc);
}

// ============================================================================
extern "C" void kernel_launch(void* const* d_in, const int* in_sizes, int n_in,
                              void* d_out, int out_size) {
  const float* feat1 = (const float*)d_in[0];
  const float* feat2 = (const float*)d_in[1];
  const float* off_w1 = (const float*)d_in[2];
  const float* off_g1 = (const float*)d_in[3];
  const float* off_b1 = (const float*)d_in[4];
  const float* off_w2 = (const float*)d_in[5];
  const float* off_g2 = (const float*)d_in[6];
  const float* off_b2 = (const float*)d_in[7];
  const float* off_w3 = (const float*)d_in[8];
  const float* off_bias3 = (const float*)d_in[9];
  const float* corr_w = (const float*)d_in[10];
  const float* corr_g = (const float*)d_in[11];
  const float* corr_b = (const float*)d_in[12];
  const float* diff_w = (const float*)d_in[13];
  const float* diff_g = (const float*)d_in[14];
  const float* diff_b = (const float*)d_in[15];
  const float* fus_w1 = (const float*)d_in[16];
  const float* fus_g1 = (const float*)d_in[17];
  const float* fus_b1 = (const float*)d_in[18];
  const float* fus_w2 = (const float*)d_in[19];
  const float* lam_w = (const float*)d_in[20];
  const float* lam_b = (const float*)d_in[21];

  float* x1;   cudaGetSymbolAddress((void**)&x1, g_x1);
  float* x2;   cudaGetSymbolAddress((void**)&x2, g_x2);
  float* pred; cudaGetSymbolAddress((void**)&pred, g_pred);
  float* cv;   cudaGetSymbolAddress((void**)&cv, g_cv);
  float* ce;   cudaGetSymbolAddress((void**)&ce, g_ce);
  float* de;   cudaGetSymbolAddress((void**)&de, g_de);
  float* fbuf; cudaGetSymbolAddress((void**)&fbuf, g_f);

  float* out_aligned = (float*)d_out;                       // B*C*HW
  float* out_flow = out_aligned + (size_t)BB * CC * HWs;    // B*2*HW
  float* out_lam = out_flow + (size_t)BB * 2 * HWs;         // B*1*HW

  const int PIX_BLOCKS = HWs / 256;  // 64

  // 1) conv1: concat(feat1,feat2) 256 -> 128, 3x3 pad1
  conv3x3_k<<<dim3(64, 128 / 16, BB), 256>>>(feat1, feat2, 128, 128, off_w1, x1, 128);
  gn_stats_k<<<BB * 32, 256>>>(x1, 128, 32);
  gn_act_k<<<(BB * 128 * HWs) / 256, 256>>>(x1, off_g1, off_b1, 128, 32, 0);

  // 2) conv2: 128 -> 64, 3x3 pad1
  conv3x3_k<<<dim3(64, 64 / 16, BB), 256>>>(x1, x1, 128, 0, off_w2, x2, 64);
  gn_stats_k<<<BB * 32, 256>>>(x2, 64, 32);
  gn_act_k<<<(BB * 64 * HWs) / 256, 256>>>(x2, off_g2, off_b2, 64, 32, 0);

  // 3) pred head: 64 -> 3, 3x3 pad1, + bias
  pred_conv_k<<<dim3(PIX_BLOCKS, 3, BB), 256>>>(x2, off_w3, off_bias3, pred);

  // 4) flow / validity / bilinear warp -> aligned (into d_out) + flow (into d_out)
  warp_k<<<dim3(PIX_BLOCKS, BB), 256>>>(feat2, pred, out_aligned, out_flow);

  // 5) cost volume: 81 channels, tiled smem version
  costvol_k<<<dim3(64, BB), 256>>>(feat1, out_aligned, cv);

  // 6) corr embed: 1x1 81 -> 64, GN, relu
  conv1x1_64_k<<<dim3(PIX_BLOCKS, BB), 256>>>(cv, corr_w, ce, 81);
  gn_stats_k<<<BB * 32, 256>>>(ce, 64, 32);
  gn_act_k<<<(BB * 64 * HWs) / 256, 256>>>(ce, corr_g, corr_b, 64, 32, 1);

  // 7) diff embed: |feat1-aligned| -> 1x1 128 -> 64, GN, relu
  diffconv_k<<<dim3(PIX_BLOCKS, BB), 256>>>(feat1, out_aligned, diff_w, de);
  gn_stats_k<<<BB * 32, 256>>>(de, 64, 32);
  gn_act_k<<<(BB * 64 * HWs) / 256, 256>>>(de, diff_g, diff_b, 64, 32, 1);

  // 8) fusion: concat(ce,de) 128 -> 128, 3x3 pad1, GN, relu
  conv3x3_k<<<dim3(64, 128 / 16, BB), 256>>>(ce, de, 64, 64, fus_w1, fbuf, 128);
  gn_stats_k<<<BB * 32, 256>>>(fbuf, 128, 32);
  gn_act_k<<<(BB * 128 * HWs) / 256, 256>>>(fbuf, fus_g1, fus_b1, 128, 32, 1);

  // 9) lam = sigmoid((fus_w2 then lam_w) . f + lam_b)  — composed 1x1 convs
  weff_k<<<1, 128>>>(fus_w2, lam_w);
  lam_k<<<dim3(PIX_BLOCKS, BB), 256>>>(fbuf, lam_b, out_lam);
}

// round 7
// speedup vs baseline: 1.0059x; 1.0059x over previous
#include <cuda_runtime.h>
#include <math.h>

#define BB 8
#define CC 128
#define HH 128
#define WW 128
#define HWs 16384
#define RR 4
#define KK 9

// ---------------- scratch (static __device__, no allocation) ----------------
__device__ float g_x1[BB * CC * HWs];     // conv1 out / gn1+silu (in place)
__device__ float g_x2[BB * 64 * HWs];     // conv2 out / gn2+silu
__device__ float g_pred[BB * 3 * HWs];    // offset head output
__device__ float g_cv[BB * 81 * HWs];     // cost volume
__device__ float g_ce[BB * 64 * HWs];     // corr embed
__device__ float g_de[BB * 64 * HWs];     // diff embed
__device__ float g_f[BB * CC * HWs];      // fusion conv out
__device__ float g_mean[256];
__device__ float g_rstd[256];
__device__ float g_weff[128];             // lam_w @ fus_w2 composed

__device__ __forceinline__ float sigmoidf_(float x) { return 1.f / (1.f + expf(-x)); }

// ---------------- generic 3x3 conv, pad=1, 2 channels per stage ----------------
// grid: (64 tiles, Cout/16, B), block 256.
// Each thread: 1 output channel x 4x4 pixel patch (16 accumulators).
__global__ void conv3x3_k(const float* __restrict__ in1, const float* __restrict__ in2,
                          int Cin1, int Cin2, const float* __restrict__ wgt,
                          float* __restrict__ out, int Cout) {
  __shared__ float s_in[2][18 * 18];
  __shared__ float s_w[2][144];
  const int Cin = Cin1 + Cin2;  // always even here
  int b = blockIdx.z;
  int co_base = blockIdx.y * 16;
  int tile = blockIdx.x;
  int ty0 = (tile >> 3) << 4;
  int tx0 = (tile & 7) << 4;
  int tid = threadIdx.x;
  int co = tid >> 4;
  int pg = tid & 15;
  int pr0 = (pg >> 2) << 2;
  int pc0 = (pg & 3) << 2;
  float acc[16];
#pragma unroll
  for (int i = 0; i < 16; i++) acc[i] = 0.f;

  for (int ci = 0; ci < Cin; ci += 2) {
    __syncthreads();
    for (int i = tid; i < 648; i += 256) {
      int buf = (i >= 324) ? 1 : 0;
      int j = i - buf * 324;
      int r = j / 18, c = j - r * 18;
      int cc2 = ci + buf;
      const float* plane = (cc2 < Cin1)
          ? in1 + ((size_t)b * Cin1 + cc2) * HWs
          : in2 + ((size_t)b * Cin2 + (cc2 - Cin1)) * HWs;
      int gy = ty0 + r - 1, gx = tx0 + c - 1;
      float v = 0.f;
      if (gy >= 0 && gy < HH && gx >= 0 && gx < WW) v = plane[gy * WW + gx];
      s_in[buf][j] = v;
    }
    // FIX (R2): strided loop — previous `if (tid < 288)` with 256 threads left
    // s_w[1][112..143] uninitialized -> NaN.
    for (int i = tid; i < 288; i += 256) {
      int buf = (i >= 144) ? 1 : 0;
      int j = i - buf * 144;
      int c2 = j / 9, k = j - c2 * 9;
      s_w[buf][j] = wgt[((size_t)(co_base + c2) * Cin + ci + buf) * 9 + k];
    }
    __syncthreads();
#pragma unroll
    for (int buf = 0; buf < 2; buf++) {
      float wreg[9];
#pragma unroll
      for (int k = 0; k < 9; k++) wreg[k] = s_w[buf][co * 9 + k];
      float patch[6][6];
#pragma unroll
      for (int r = 0; r < 6; r++)
#pragma unroll
        for (int c = 0; c < 6; c++)
          patch[r][c] = s_in[buf][(pr0 + r) * 18 + pc0 + c];
#pragma unroll
      for (int ky = 0; ky < 3; ky++)
#pragma unroll
        for (int kx = 0; kx < 3; kx++) {
          float wv = wreg[ky * 3 + kx];
#pragma unroll
          for (int pr = 0; pr < 4; pr++)
#pragma unroll
            for (int pc = 0; pc < 4; pc++)
              acc[pr * 4 + pc] += patch[pr + ky][pc + kx] * wv;
        }
    }
  }
  float* op = out + ((size_t)b * Cout + co_base + co) * HWs;
#pragma unroll
  for (int pr = 0; pr < 4; pr++)
#pragma unroll
    for (int pc = 0; pc < 4; pc++)
      op[(ty0 + pr0 + pr) * WW + tx0 + pc0 + pc] = acc[pr * 4 + pc];
}

// ---------------- GroupNorm stats (one block per (b, group)) ----------------
__global__ void gn_stats_k(const float* __restrict__ x, int C, int G) {
  __shared__ double s_s[256];
  __shared__ double s_q[256];
  int bg = blockIdx.x;
  int b = bg / G, g = bg % G;
  int cpg = C / G;
  long n = (long)cpg * HWs;
  const float* base = x + ((size_t)b * C + (size_t)g * cpg) * HWs;
  double s = 0, q = 0;
  for (long i = threadIdx.x; i < n; i += 256) {
    double v = base[i];
    s += v;
    q += v * v;
  }
  s_s[threadIdx.x] = s;
  s_q[threadIdx.x] = q;
  __syncthreads();
  for (int off = 128; off > 0; off >>= 1) {
    if (threadIdx.x < off) {
      s_s[threadIdx.x] += s_s[threadIdx.x + off];
      s_q[threadIdx.x] += s_q[threadIdx.x + off];
    }
    __syncthreads();
  }
  if (threadIdx.x == 0) {
    double m = s_s[0] / (double)n;
    double var = s_q[0] / (double)n - m * m;
    g_mean[bg] = (float)m;
    g_rstd[bg] = (float)rsqrt(var + 1e-5);
  }
}

// ---------------- GroupNorm apply + activation (0=silu, 1=relu) -------------
__global__ void gn_act_k(float* __restrict__ x, const float* __restrict__ gamma,
                         const float* __restrict__ beta, int C, int G, int act) {
  long idx = (long)blockIdx.x * 256 + threadIdx.x;
  int cpg = C / G;
  long chw = (long)C * HWs;
  int b = (int)(idx / chw);
  int c = (int)((idx % chw) / HWs);
  int bg = b * G + c / cpg;
  float v = x[idx];
  v = (v - g_mean[bg]) * g_rstd[bg] * gamma[c] + beta[c];
  if (act == 0)
    v = v * sigmoidf_(v);
  else
    v = fmaxf(v, 0.f);
  x[idx] = v;
}

// ---------------- offset head final conv (64 -> 3, 3x3, pad=1) + bias -------
__global__ void pred_conv_k(const float* __restrict__ in, const float* __restrict__ wgt,
                            const float* __restrict__ bias, float* __restrict__ out) {
  __shared__ float s_w[576];
  int co = blockIdx.y, b = blockIdx.z;
  for (int i = threadIdx.x; i < 576; i += 256) s_w[i] = wgt[co * 576 + i];
  __syncthreads();
  int p = blockIdx.x * 256 + threadIdx.x;
  int h = p >> 7, w = p & 127;
  float acc = bias[co];
  for (int ci = 0; ci < 64; ci++) {
    const float* pl = in + ((size_t)b * 64 + ci) * HWs;
#pragma unroll
    for (int ky = 0; ky < 3; ky++) {
      int y = h + ky - 1;
      if (y < 0 || y >= HH) continue;
#pragma unroll
      for (int kx = 0; kx < 3; kx++) {
        int xx = w + kx - 1;
        if (xx < 0 || xx >= WW) continue;
        acc += pl[y * WW + xx] * s_w[ci * 9 + ky * 3 + kx];
      }
    }
  }
  out[((size_t)b * 3 + co) * HWs + p] = acc;
}

// ---------------- flow + validity + bilinear warp ----------------
__global__ void warp_k(const float* __restrict__ feat2, const float* __restrict__ pred,
                       float* __restrict__ out_aligned, float* __restrict__ out_flow) {
  int b = blockIdx.y;
  int p = blockIdx.x * 256 + threadIdx.x;
  int h = p >> 7, w = p & 127;
  const float* pb = pred + (size_t)b * 3 * HWs;
  float f0 = pb[p], f1 = pb[HWs + p], pv = pb[2 * HWs + p];
  float val = sigmoidf_(pv);
  out_flow[((size_t)b * 2) * HWs + p] = f0;
  out_flow[((size_t)b * 2 + 1) * HWs + p] = f1;
  float px = (float)w + f0, py = (float)h + f1;
  float x0f = floorf(px), y0f = floorf(py);
  float wx = px - x0f, wy = py - y0f;
  int x0 = (int)x0f, y0 = (int)y0f;
  bool vx0 = (x0 >= 0) && (x0 < WW);
  bool vx1 = (x0 + 1 >= 0) && (x0 + 1 < WW);
  bool vy0 = (y0 >= 0) && (y0 < HH);
  bool vy1 = (y0 + 1 >= 0) && (y0 + 1 < HH);
  int xc0 = min(max(x0, 0), WW - 1), xc1 = min(max(x0 + 1, 0), WW - 1);
  int yc0 = min(max(y0, 0), HH - 1), yc1 = min(max(y0 + 1, 0), HH - 1);
  float w00 = (1.f - wx) * (1.f - wy) * ((vx0 && vy0) ? 1.f : 0.f);
  float w10 = wx * (1.f - wy) * ((vx1 && vy0) ? 1.f : 0.f);
  float w01 = (1.f - wx) * wy * ((vx0 && vy1) ? 1.f : 0.f);
  float w11 = wx * wy * ((vx1 && vy1) ? 1.f : 0.f);
  int i00 = yc0 * WW + xc0, i10 = yc0 * WW + xc1;
  int i01 = yc1 * WW + xc0, i11 = yc1 * WW + xc1;
  const float* f2b = feat2 + (size_t)b * CC * HWs;
  float* ob = out_aligned + (size_t)b * CC * HWs;
  for (int c = 0; c < CC; c++) {
    const float* im = f2b + (size_t)c * HWs;
    float s = __ldg(&im[i00]) * w00 + __ldg(&im[i10]) * w10 +
              __ldg(&im[i01]) * w01 + __ldg(&im[i11]) * w11;
    ob[(size_t)c * HWs + p] = s * val;
  }
}

// ---------------- cost volume: tiled, 81 accumulators per thread ----------------
// grid: (64 tiles, B), block 256 = 16x16 pixels.
__global__ void costvol_k(const float* __restrict__ f1, const float* __restrict__ aligned,
                          float* __restrict__ cv) {
  __shared__ float s_al[24 * 24];
  int b = blockIdx.y;
  int tile = blockIdx.x;
  int ty0 = (tile >> 3) << 4;
  int tx0 = (tile & 7) << 4;
  int tid = threadIdx.x;
  int ty = tid >> 4, tx = tid & 15;
  float acc[81];
#pragma unroll
  for (int k = 0; k < 81; k++) acc[k] = 0.f;

  for (int c = 0; c < CC; c++) {
    const float* apl = aligned + ((size_t)b * CC + c) * HWs;
    __syncthreads();
    for (int i = tid; i < 576; i += 256) {
      int r = i / 24, cc = i - r * 24;
      int gy = ty0 + r - RR, gx = tx0 + cc - RR;
      float v = 0.f;
      if (gy >= 0 && gy < HH && gx >= 0 && gx < WW) v = apl[gy * WW + gx];
      s_al[i] = v;
    }
    __syncthreads();
    float f1v = f1[((size_t)b * CC + c) * HWs + (ty0 + ty) * WW + tx0 + tx];
#pragma unroll
    for (int dy = 0; dy < KK; dy++)
#pragma unroll
      for (int dx = 0; dx < KK; dx++)
        acc[dy * KK + dx] += f1v * s_al[(ty + dy) * 24 + tx + dx];
  }
  size_t pbase = (size_t)(ty0 + ty) * WW + tx0 + tx;
#pragma unroll
  for (int k = 0; k < 81; k++)
    cv[((size_t)b * 81 + k) * HWs + pbase] = acc[k] * (1.f / (float)CC);
}

// ---------------- generic 1x1 conv to 64 channels ----------------
__global__ void conv1x1_64_k(const float* __restrict__ in, const float* __restrict__ wgt,
                             float* __restrict__ out, int Cin) {
  __shared__ float s_w[64 * 128];
  int b = blockIdx.y;
  for (int i = threadIdx.x; i < 64 * Cin; i += 256) s_w[i] = wgt[i];
  __syncthreads();
  int p = blockIdx.x * 256 + threadIdx.x;
  float acc[64];
#pragma unroll
  for (int i = 0; i < 64; i++) acc[i] = 0.f;
  const float* ib = in + (size_t)b * Cin * HWs + p;
  for (int ci = 0; ci < Cin; ci++) {
    float v = __ldg(&ib[(size_t)ci * HWs]);
#pragma unroll
    for (int co = 0; co < 64; co++) acc[co] += v * s_w[co * Cin + ci];
  }
  float* ob = out + (size_t)b * 64 * HWs + p;
#pragma unroll
  for (int co = 0; co < 64; co++) ob[(size_t)co * HWs] = acc[co];
}

// ---------------- diff (|f1 - aligned|) then 1x1 conv 128->64 ----------------
__global__ void diffconv_k(const float* __restrict__ f1, const float* __restrict__ aligned,
                           const float* __restrict__ wgt, float* __restrict__ out) {
  __shared__ float s_w[64 * 128];
  int b = blockIdx.y;
  for (int i = threadIdx.x; i < 64 * 128; i += 256) s_w[i] = wgt[i];
  __syncthreads();
  int p = blockIdx.x * 256 + threadIdx.x;
  float acc[64];
#pragma unroll
  for (int i = 0; i < 64; i++) acc[i] = 0.f;
  const float* fb = f1 + (size_t)b * CC * HWs + p;
  const float* ab = aligned + (size_t)b * CC * HWs + p;
  for (int ci = 0; ci < 128; ci++) {
    float v = fabsf(__ldg(&fb[(size_t)ci * HWs]) - __ldg(&ab[(size_t)ci * HWs]));
#pragma unroll
    for (int co = 0; co < 64; co++) acc[co] += v * s_w[co * 128 + ci];
  }
  float* ob = out + (size_t)b * 64 * HWs + p;
#pragma unroll
  for (int co = 0; co < 64; co++) ob[(size_t)co * HWs] = acc[co];
}

// ---------------- compose lam_w @ fus_w2 (both 1x1) ----------------
__global__ void weff_k(const float* __restrict__ fus_w2, const float* __restrict__ lam_w) {
  int ci = threadIdx.x;  // 128 threads
  float s = 0.f;
  for (int co = 0; co < 128; co++) s += lam_w[co] * fus_w2[co * 128 + ci];
  g_weff[ci] = s;
}

// ---------------- lam = sigmoid(f . weff + b) ----------------
__global__ void lam_k(const float* __restrict__ f, const float* __restrict__ lam_b,
                      float* __restrict__ out) {
  __shared__ float s_w[128];
  if (threadIdx.x < 128) s_w[threadIdx.x] = g_weff[threadIdx.x];
  __syncthreads();
  int b = blockIdx.y;
  int p = blockIdx.x * 256 + threadIdx.x;
  const float* fb = f + (size_t)b * 128 * HWs + p;
  float acc = lam_b[0];
  for (int ci = 0; ci < 128; ci++) acc += __ldg(&fb[(size_t)ci * HWs]) * s_w[ci];
  out[(size_t)b * HWs + p] = sigmoidf_(acc);
}

// ============================================================================
extern "C" void kernel_launch(void* const* d_in, const int* in_sizes, int n_in,
                              void* d_out, int out_size) {
  const float* feat1 = (const float*)d_in[0];
  const float* feat2 = (const float*)d_in[1];
  const float* off_w1 = (const float*)d_in[2];
  const float* off_g1 = (const float*)d_in[3];
  const float* off_b1 = (const float*)d_in[4];
  const float* off_w2 = (const float*)d_in[5];
  const float* off_g2 = (const float*)d_in[6];
  const float* off_b2 = (const float*)d_in[7];
  const float* off_w3 = (const float*)d_in[8];
  const float* off_bias3 = (const float*)d_in[9];
  const float* corr_w = (const float*)d_in[10];
  const float* corr_g = (const float*)d_in[11];
  const float* corr_b = (const float*)d_in[12];
  const float* diff_w = (const float*)d_in[13];
  const float* diff_g = (const float*)d_in[14];
  const float* diff_b = (const float*)d_in[15];
  const float* fus_w1 = (const float*)d_in[16];
  const float* fus_g1 = (const float*)d_in[17];
  const float* fus_b1 = (const float*)d_in[18];
  const float* fus_w2 = (const float*)d_in[19];
  const float* lam_w = (const float*)d_in[20];
  const float* lam_b = (const float*)d_in[21];

  float* x1;   cudaGetSymbolAddress((void**)&x1, g_x1);
  float* x2;   cudaGetSymbolAddress((void**)&x2, g_x2);
  float* pred; cudaGetSymbolAddress((void**)&pred, g_pred);
  float* cv;   cudaGetSymbolAddress((void**)&cv, g_cv);
  float* ce;   cudaGetSymbolAddress((void**)&ce, g_ce);
  float* de;   cudaGetSymbolAddress((void**)&de, g_de);
  float* fbuf; cudaGetSymbolAddress((void**)&fbuf, g_f);

  float* out_aligned = (float*)d_out;                       // B*C*HW
  float* out_flow = out_aligned + (size_t)BB * CC * HWs;    // B*2*HW
  float* out_lam = out_flow + (size_t)BB * 2 * HWs;         // B*1*HW

  const int PIX_BLOCKS = HWs / 256;  // 64

  // 1) conv1: concat(feat1,feat2) 256 -> 128, 3x3 pad1
  conv3x3_k<<<dim3(64, 128 / 16, BB), 256>>>(feat1, feat2, 128, 128, off_w1, x1, 128);
  gn_stats_k<<<BB * 32, 256>>>(x1, 128, 32);
  gn_act_k<<<(BB * 128 * HWs) / 256, 256>>>(x1, off_g1, off_b1, 128, 32, 0);

  // 2) conv2: 128 -> 64, 3x3 pad1
  conv3x3_k<<<dim3(64, 64 / 16, BB), 256>>>(x1, x1, 128, 0, off_w2, x2, 64);
  gn_stats_k<<<BB * 32, 256>>>(x2, 64, 32);
  gn_act_k<<<(BB * 64 * HWs) / 256, 256>>>(x2, off_g2, off_b2, 64, 32, 0);

  // 3) pred head: 64 -> 3, 3x3 pad1, + bias
  pred_conv_k<<<dim3(PIX_BLOCKS, 3, BB), 256>>>(x2, off_w3, off_bias3, pred);

  // 4) flow / validity / bilinear warp -> aligned (into d_out) + flow (into d_out)
  warp_k<<<dim3(PIX_BLOCKS, BB), 256>>>(feat2, pred, out_aligned, out_flow);

  // 5) cost volume: 81 channels, tiled smem version
  costvol_k<<<dim3(64, BB), 256>>>(feat1, out_aligned, cv);

  // 6) corr embed: 1x1 81 -> 64, GN, relu
  conv1x1_64_k<<<dim3(PIX_BLOCKS, BB), 256>>>(cv, corr_w, ce, 81);
  gn_stats_k<<<BB * 32, 256>>>(ce, 64, 32);
  gn_act_k<<<(BB * 64 * HWs) / 256, 256>>>(ce, corr_g, corr_b, 64, 32, 1);

  // 7) diff embed: |feat1-aligned| -> 1x1 128 -> 64, GN, relu
  diffconv_k<<<dim3(PIX_BLOCKS, BB), 256>>>(feat1, out_aligned, diff_w, de);
  gn_stats_k<<<BB * 32, 256>>>(de, 64, 32);
  gn_act_k<<<(BB * 64 * HWs) / 256, 256>>>(de, diff_g, diff_b, 64, 32, 1);

  // 8) fusion: concat(ce,de) 128 -> 128, 3x3 pad1, GN, relu
  conv3x3_k<<<dim3(64, 128 / 16, BB), 256>>>(ce, de, 64, 64, fus_w1, fbuf, 128);
  gn_stats_k<<<BB * 32, 256>>>(fbuf, 128, 32);
  gn_act_k<<<(BB * 128 * HWs) / 256, 256>>>(fbuf, fus_g1, fus_b1, 128, 32, 1);

  // 9) lam = sigmoid((fus_w2 then lam_w) . f + lam_b)  — composed 1x1 convs
  weff_k<<<1, 128>>>(fus_w2, lam_w);
  lam_k<<<dim3(PIX_BLOCKS, BB), 256>>>(fbuf, lam_b, out_lam);
}